// round 7
// baseline (speedup 1.0000x reference)
#include <cuda_runtime.h>

// Scratch (no allocations allowed): s = scaled B-projection, k = conv taps.
__device__ __align__(16) float g_s[4 * 16 * 64];      // [b][u][n]
__device__ __align__(16) float g_k[4 * 16 * 1024];    // [b][u][m]

#define TAPS 16
#define BQ 4
#define LQ 2048
#define DMQ 1024
#define NQ 64

// ---------------------------------------------------------------------------
// K1: s[b,u,n] = (dot(x[b,u,:], W_B[n,:]) + b_B[n]) * exp(u * log_A[n])
// grid = 1024: (64 (b,u)) x (16 n-groups of 4). Block = 128 = 4 warps,
// one warp per n. Decay cutoff: if u*log_A[n] < -30 the tap contribution is
// < e^-30 of the signal -> s := 0 and the warp exits without touching memory.
// (Runtime test on the actual log_A values; warp-uniform branch.)
// ---------------------------------------------------------------------------
__global__ void __launch_bounds__(128) s4_k1(const float* __restrict__ x,
                                             const float* __restrict__ W_B,
                                             const float* __restrict__ b_B,
                                             const float* __restrict__ log_A) {
    int bu = blockIdx.x >> 4;            // 0..63
    int ng = blockIdx.x & 15;            // n-group of 4
    int b = bu >> 4;
    int u = bu & 15;

    int w = threadIdx.x >> 5;
    int lane = threadIdx.x & 31;
    int n = ng * 4 + w;

    float a = (float)u * log_A[n];
    if (a < -30.0f) {                    // negligible tap: exact-enough zero
        if (lane == 0) g_s[bu * NQ + n] = 0.0f;
        return;
    }

    const float4* xr = reinterpret_cast<const float4*>(x + ((size_t)b * LQ + u) * DMQ);
    const float4* wr = reinterpret_cast<const float4*>(W_B + (size_t)n * DMQ);

    float4 xv[8], wv[8];
    #pragma unroll
    for (int j = 0; j < 8; j++) xv[j] = xr[lane + 32 * j];   // 16 independent
    #pragma unroll
    for (int j = 0; j < 8; j++) wv[j] = wr[lane + 32 * j];   // LDG.128 total

    float p0 = 0.0f, p1 = 0.0f;
    #pragma unroll
    for (int j = 0; j < 8; j++) {
        p0 += xv[j].x * wv[j].x + xv[j].y * wv[j].y;
        p1 += xv[j].z * wv[j].z + xv[j].w * wv[j].w;
    }
    float p = p0 + p1;
    #pragma unroll
    for (int off = 16; off; off >>= 1) p += __shfl_xor_sync(0xFFFFFFFFu, p, off);

    if (lane == 0) {
        g_s[bu * NQ + n] = (p + b_B[n]) * expf(a);
    }
}

// ---------------------------------------------------------------------------
// K2: k[b,u,m] = sum_n s[b,u,n] * C[n,m]
// grid = (16 m-tiles of 64, 16 (b, u-group of 4)), block = (64, 4): ty = u in
// group. Skip n where s[n] == 0 (exact; warp-uniform since u is per-ty-row) --
// kills ~85% of the C loads for u >= 1.
// ---------------------------------------------------------------------------
__global__ void __launch_bounds__(256) s4_k2(const float* __restrict__ C) {
    int b  = blockIdx.y >> 2;
    int ug = blockIdx.y & 3;
    int bu = b * TAPS + ug * 4 + threadIdx.y;
    int m  = blockIdx.x * 64 + threadIdx.x;

    __shared__ float s[4][NQ];
    int tid = threadIdx.y * 64 + threadIdx.x;
    if (tid < 4 * NQ)
        s[tid >> 6][tid & 63] = g_s[(b * TAPS + ug * 4) * NQ + tid];
    __syncthreads();

    float acc = 0.0f;
    const float* sr = s[threadIdx.y];
    #pragma unroll 8
    for (int n = 0; n < NQ; n++) {
        float sv = sr[n];
        if (sv != 0.0f) acc += sv * C[(size_t)n * DMQ + m];
    }

    g_k[(size_t)bu * DMQ + m] = acc;
}

// ---------------------------------------------------------------------------
// K3: 16-tap per-channel causal FIR + D skip, packed f32x2 math.
// Thread = one channel pair (2 adjacent m) x 16 consecutive t outputs.
// Taps CACHED in registers (streamed version measured ~2.4x slower).
// grid = (2 c-tiles, 128 t-tiles, 4 b), block = 256. ~DRAM-floor bound.
// ---------------------------------------------------------------------------
typedef unsigned long long u64t;

__device__ __forceinline__ u64t ffma2(u64t a, u64t b, u64t c) {
    u64t d;
    asm("fma.rn.f32x2 %0, %1, %2, %3;" : "=l"(d) : "l"(a), "l"(b), "l"(c));
    return d;
}
__device__ __forceinline__ u64t fmul2(u64t a, u64t b) {
    u64t d;
    asm("mul.rn.f32x2 %0, %1, %2;" : "=l"(d) : "l"(a), "l"(b));
    return d;
}

__global__ void __launch_bounds__(256) s4_k3(const float* __restrict__ x,
                                             const float* __restrict__ D,
                                             float* __restrict__ out) {
    const int S = DMQ / 2;                       // row stride in pairs
    int c  = blockIdx.x * 256 + threadIdx.x;     // 0..511 channel pair
    int t0 = blockIdx.y * 16;
    int b  = blockIdx.z;

    const u64t* xp = reinterpret_cast<const u64t*>(x) + (size_t)b * LQ * S + c;
    const u64t* kp = reinterpret_cast<const u64t*>(g_k) + (size_t)b * TAPS * S + c;

    u64t kr[TAPS];
    #pragma unroll
    for (int u = 0; u < TAPS; u++) kr[u] = kp[(size_t)u * S];

    u64t dp = reinterpret_cast<const u64t*>(D)[c];

    // x window: t = t0-15 .. t0+15  (31 pairs), zero below t=0
    u64t win[31];
    #pragma unroll
    for (int i = 0; i < 31; i++) {
        int t = t0 - 15 + i;
        win[i] = (t >= 0) ? xp[(size_t)t * S] : 0ull;   // 0x0 == {+0.f,+0.f}
    }

    u64t acc[16];
    #pragma unroll
    for (int j = 0; j < 16; j++) acc[j] = fmul2(win[15 + j], dp);   // D skip

    #pragma unroll
    for (int u = 0; u < TAPS; u++) {
        #pragma unroll
        for (int j = 0; j < 16; j++)
            acc[j] = ffma2(kr[u], win[15 + j - u], acc[j]);
    }

    u64t* op = reinterpret_cast<u64t*>(out) + (size_t)b * LQ * S + c;
    #pragma unroll
    for (int j = 0; j < 16; j++) op[(size_t)(t0 + j) * S] = acc[j];
}

// ---------------------------------------------------------------------------
extern "C" void kernel_launch(void* const* d_in, const int* in_sizes, int n_in,
                              void* d_out, int out_size) {
    const float* x     = (const float*)d_in[0];   // (4, 2048, 1024)
    const float* W_B   = (const float*)d_in[1];   // (64, 1024)
    const float* b_B   = (const float*)d_in[2];   // (64,)
    const float* C     = (const float*)d_in[3];   // (64, 1024)
    const float* D     = (const float*)d_in[4];   // (1024,)
    const float* log_A = (const float*)d_in[5];   // (64,)
    float* out = (float*)d_out;

    s4_k1<<<1024, 128>>>(x, W_B, b_B, log_A);
    s4_k2<<<dim3(16, 16), dim3(64, 4)>>>(C);
    s4_k3<<<dim3(2, 128, 4), 256>>>(x, D, out);
}

// round 8
// speedup vs baseline: 1.2122x; 1.2122x over previous
#include <cuda_runtime.h>

// Scratch (no allocations allowed): k = conv taps.
__device__ __align__(16) float g_k[4 * 16 * 1024];    // [b][u][m]

#define TAPS 16
#define BQ 4
#define LQ 2048
#define DMQ 1024
#define NQ 64

// ---------------------------------------------------------------------------
// K12 (fused): s[n] = (dot(x[b,u,:], W_B[n,:]) + b_B[n]) * exp(u*log_A[n])
// kept in smem, then k[b,u,m] = sum_{n<ncnt} s[n] * C[n,m].
// grid = 64 (bu), block = 512 = 16 warps (warp w owns n = 4w..4w+3).
// Sparsity = dynamic loop BOUND ncnt (runtime-tested cutoff u*log_A < -30),
// never a per-iteration branch around loads.
// ---------------------------------------------------------------------------
__global__ void __launch_bounds__(512) s4_k12(const float* __restrict__ x,
                                              const float* __restrict__ W_B,
                                              const float* __restrict__ b_B,
                                              const float* __restrict__ C,
                                              const float* __restrict__ log_A) {
    cudaTriggerProgrammaticLaunchCompletion();   // release PDL secondary ASAP

    int bu = blockIdx.x;                 // b*16 + u
    int b = bu >> 4;
    int u = bu & 15;
    int tid = threadIdx.x;
    int w = tid >> 5;
    int lane = tid & 31;

    __shared__ float4 xs[DMQ / 4];       // 4 KB x row
    __shared__ float s_sm[NQ];
    __shared__ int s_ncnt;

    const float4* xr = reinterpret_cast<const float4*>(x + ((size_t)b * LQ + u) * DMQ);
    if (tid < 256) xs[tid] = xr[tid];

    if (tid == 0) {                      // active-n count from actual log_A
        int c = 0;
        #pragma unroll
        for (int n = 0; n < NQ; n++)
            if ((float)u * log_A[n] >= -30.0f) c = n + 1;
        s_ncnt = c;
    }
    __syncthreads();
    int ncnt = s_ncnt;

    // ---- Phase A: dots (warp-uniform skip of fully-inactive warps) ----
    int n0 = w * 4;
    if (n0 < ncnt) {
        float p[4];
        #pragma unroll
        for (int q = 0; q < 2; q++) {
            const float4* wr0 = reinterpret_cast<const float4*>(W_B + (size_t)(n0 + 2 * q)     * DMQ);
            const float4* wr1 = reinterpret_cast<const float4*>(W_B + (size_t)(n0 + 2 * q + 1) * DMQ);
            float4 wa[8], wb[8];
            #pragma unroll
            for (int j = 0; j < 8; j++) wa[j] = wr0[lane + 32 * j];   // 16 front-
            #pragma unroll
            for (int j = 0; j < 8; j++) wb[j] = wr1[lane + 32 * j];   // batched LDG.128
            float pa = 0.f, pa2 = 0.f, pb = 0.f, pb2 = 0.f;
            #pragma unroll
            for (int j = 0; j < 8; j++) {
                float4 a = xs[lane + 32 * j];
                pa  += a.x * wa[j].x + a.y * wa[j].y;
                pa2 += a.z * wa[j].z + a.w * wa[j].w;
                pb  += a.x * wb[j].x + a.y * wb[j].y;
                pb2 += a.z * wb[j].z + a.w * wb[j].w;
            }
            p[2 * q]     = pa + pa2;
            p[2 * q + 1] = pb + pb2;
        }
        #pragma unroll
        for (int off = 16; off; off >>= 1) {
            #pragma unroll
            for (int q = 0; q < 4; q++) p[q] += __shfl_xor_sync(0xFFFFFFFFu, p[q], off);
        }
        if (lane < 4) {
            int n = n0 + lane;
            if (n < ncnt)
                s_sm[n] = (p[lane] + b_B[n]) * expf((float)u * log_A[n]);
        }
    }
    __syncthreads();

    // ---- Phase B: k[bu, m] for m-pair = tid, trip count = ncnt ----
    const float2* C2 = reinterpret_cast<const float2*>(C);
    float ax = 0.f, ay = 0.f;
    #pragma unroll 8
    for (int n = 0; n < ncnt; n++) {
        float sv = s_sm[n];
        float2 cv = C2[(size_t)n * (DMQ / 2) + tid];
        ax += sv * cv.x;
        ay += sv * cv.y;
    }
    reinterpret_cast<float2*>(g_k)[(size_t)bu * (DMQ / 2) + tid] = make_float2(ax, ay);
}

// ---------------------------------------------------------------------------
// K3: 16-tap per-channel causal FIR + D skip, packed f32x2 math.
// PDL secondary: loads its x window + D BEFORE cudaGridDependencySynchronize()
// (overlaps with K12), then taps after the sync.
// grid = (2 c-tiles, 128 t-tiles, 4 b), block = 256. ~DRAM-floor bound.
// ---------------------------------------------------------------------------
typedef unsigned long long u64t;

__device__ __forceinline__ u64t ffma2(u64t a, u64t b, u64t c) {
    u64t d;
    asm("fma.rn.f32x2 %0, %1, %2, %3;" : "=l"(d) : "l"(a), "l"(b), "l"(c));
    return d;
}
__device__ __forceinline__ u64t fmul2(u64t a, u64t b) {
    u64t d;
    asm("mul.rn.f32x2 %0, %1, %2;" : "=l"(d) : "l"(a), "l"(b));
    return d;
}

__global__ void __launch_bounds__(256) s4_k3(const float* __restrict__ x,
                                             const float* __restrict__ D,
                                             float* __restrict__ out) {
    const int S = DMQ / 2;                       // row stride in pairs
    int c  = blockIdx.x * 256 + threadIdx.x;     // 0..511 channel pair
    int t0 = blockIdx.y * 16;
    int b  = blockIdx.z;

    const u64t* xp = reinterpret_cast<const u64t*>(x) + (size_t)b * LQ * S + c;

    u64t dp = reinterpret_cast<const u64t*>(D)[c];

    // x window: t = t0-15 .. t0+15  (31 pairs), zero below t=0  [pre-sync]
    u64t win[31];
    #pragma unroll
    for (int i = 0; i < 31; i++) {
        int t = t0 - 15 + i;
        win[i] = (t >= 0) ? xp[(size_t)t * S] : 0ull;   // 0x0 == {+0.f,+0.f}
    }

    u64t acc[16];
    #pragma unroll
    for (int j = 0; j < 16; j++) acc[j] = fmul2(win[15 + j], dp);   // D skip

    cudaGridDependencySynchronize();             // wait for K12's g_k

    const u64t* kp = reinterpret_cast<const u64t*>(g_k) + (size_t)b * TAPS * S + c;
    u64t kr[TAPS];
    #pragma unroll
    for (int u = 0; u < TAPS; u++) kr[u] = kp[(size_t)u * S];

    #pragma unroll
    for (int u = 0; u < TAPS; u++) {
        #pragma unroll
        for (int j = 0; j < 16; j++)
            acc[j] = ffma2(kr[u], win[15 + j - u], acc[j]);
    }

    u64t* op = reinterpret_cast<u64t*>(out) + (size_t)b * LQ * S + c;
    #pragma unroll
    for (int j = 0; j < 16; j++) op[(size_t)(t0 + j) * S] = acc[j];
}

// ---------------------------------------------------------------------------
extern "C" void kernel_launch(void* const* d_in, const int* in_sizes, int n_in,
                              void* d_out, int out_size) {
    const float* x     = (const float*)d_in[0];   // (4, 2048, 1024)
    const float* W_B   = (const float*)d_in[1];   // (64, 1024)
    const float* b_B   = (const float*)d_in[2];   // (64,)
    const float* C     = (const float*)d_in[3];   // (64, 1024)
    const float* D     = (const float*)d_in[4];   // (1024,)
    const float* log_A = (const float*)d_in[5];   // (64,)
    float* out = (float*)d_out;

    s4_k12<<<64, 512>>>(x, W_B, b_B, C, log_A);

    // K3 with programmatic dependent launch (overlap x-window loads with K12).
    cudaLaunchConfig_t cfg = {};
    cfg.gridDim  = dim3(2, 128, 4);
    cfg.blockDim = dim3(256, 1, 1);
    cfg.dynamicSmemBytes = 0;
    cfg.stream = 0;
    cudaLaunchAttribute attr[1];
    attr[0].id = cudaLaunchAttributeProgrammaticStreamSerialization;
    attr[0].val.programmaticStreamSerializationAllowed = 1;
    cfg.attrs = attr;
    cfg.numAttrs = 1;
    cudaError_t e = cudaLaunchKernelEx(&cfg, s4_k3, x, D, (float*)out);
    if (e != cudaSuccess) {
        (void)cudaGetLastError();                 // clear; fall back to serial launch
        s4_k3<<<dim3(2, 128, 4), 256>>>(x, D, out);
    }
}

// round 9
// speedup vs baseline: 1.4283x; 1.1783x over previous
#include <cuda_runtime.h>

// Scratch (no allocations allowed): s = scaled B-projection, k = conv taps.
__device__ __align__(16) float g_s[4 * 16 * 64];      // [b][u][n]
__device__ __align__(16) float g_k[4 * 16 * 1024];    // [b][u][m]

#define TAPS 16
#define BQ 4
#define LQ 2048
#define DMQ 1024
#define NQ 64

// ---------------------------------------------------------------------------
// K1: s[b,u,n] = (dot(x[b,u,:], W_B[n,:]) + b_B[n]) * exp(u * log_A[n])
// R6 version (measured 5.8us): grid 1024, block 128, no smem/barrier,
// 16 front-batched LDG.128 per lane. Trigger at entry releases K2 early.
// ---------------------------------------------------------------------------
__global__ void __launch_bounds__(128) s4_k1(const float* __restrict__ x,
                                             const float* __restrict__ W_B,
                                             const float* __restrict__ b_B,
                                             const float* __restrict__ log_A) {
    cudaTriggerProgrammaticLaunchCompletion();

    int bu = blockIdx.x >> 4;            // 0..63
    int ng = blockIdx.x & 15;            // n-group of 4
    int b = bu >> 4;
    int u = bu & 15;

    int w = threadIdx.x >> 5;
    int lane = threadIdx.x & 31;
    int n = ng * 4 + w;

    const float4* xr = reinterpret_cast<const float4*>(x + ((size_t)b * LQ + u) * DMQ);
    const float4* wr = reinterpret_cast<const float4*>(W_B + (size_t)n * DMQ);

    float4 xv[8], wv[8];
    #pragma unroll
    for (int j = 0; j < 8; j++) xv[j] = xr[lane + 32 * j];   // 16 independent
    #pragma unroll
    for (int j = 0; j < 8; j++) wv[j] = wr[lane + 32 * j];   // LDG.128 total

    float p0 = 0.0f, p1 = 0.0f;
    #pragma unroll
    for (int j = 0; j < 8; j++) {
        p0 += xv[j].x * wv[j].x + xv[j].y * wv[j].y;
        p1 += xv[j].z * wv[j].z + xv[j].w * wv[j].w;
    }
    float p = p0 + p1;
    #pragma unroll
    for (int off = 16; off; off >>= 1) p += __shfl_xor_sync(0xFFFFFFFFu, p, off);

    if (lane == 0) {
        float e = expf((float)u * log_A[n]);   // underflows to 0 like the reference
        g_s[bu * NQ + n] = (p + b_B[n]) * e;
    }
}

// ---------------------------------------------------------------------------
// K2: k[b,u,m] = sum_n s[b,u,n] * C[n,m]
// grid = (16 m-tiles of 64, 16 (b, u-group of 4)), block = (64, 4).
// ALL C traffic (64 regs/thread) loaded PRE-sync -> overlaps K1 under PDL.
// Dense loop, no per-iteration guards (twice-measured lesson).
// ---------------------------------------------------------------------------
__global__ void __launch_bounds__(256) s4_k2(const float* __restrict__ C) {
    cudaTriggerProgrammaticLaunchCompletion();

    int b  = blockIdx.y >> 2;
    int ug = blockIdx.y & 3;
    int bu = b * TAPS + ug * 4 + threadIdx.y;
    int m  = blockIdx.x * 64 + threadIdx.x;

    float cv[NQ];
    #pragma unroll
    for (int n = 0; n < NQ; n++) cv[n] = C[(size_t)n * DMQ + m];   // pre-sync

    cudaGridDependencySynchronize();     // wait for K1's g_s

    __shared__ float s[4][NQ];
    int tid = threadIdx.y * 64 + threadIdx.x;
    if (tid < 4 * NQ)
        s[tid >> 6][tid & 63] = g_s[(b * TAPS + ug * 4) * NQ + tid];
    __syncthreads();

    float acc = 0.0f;
    const float* sr = s[threadIdx.y];
    #pragma unroll
    for (int n = 0; n < NQ; n++) acc += sr[n] * cv[n];

    g_k[(size_t)bu * DMQ + m] = acc;
}

// ---------------------------------------------------------------------------
// K3: 16-tap per-channel causal FIR + D skip, packed f32x2 math.
// ROLLING 16-slot x window (j-outer) cuts live regs 126 -> ~80;
// __launch_bounds__(256,3) -> 3 blocks/SM (occ ceiling 33% -> 50%).
// grid = (2 c-tiles, 128 t-tiles, 4 b), block = 256.
// ---------------------------------------------------------------------------
typedef unsigned long long u64t;

__device__ __forceinline__ u64t ffma2(u64t a, u64t b, u64t c) {
    u64t d;
    asm("fma.rn.f32x2 %0, %1, %2, %3;" : "=l"(d) : "l"(a), "l"(b), "l"(c));
    return d;
}
__device__ __forceinline__ u64t fmul2(u64t a, u64t b) {
    u64t d;
    asm("mul.rn.f32x2 %0, %1, %2;" : "=l"(d) : "l"(a), "l"(b));
    return d;
}

__global__ void __launch_bounds__(256, 3) s4_k3(const float* __restrict__ x,
                                                const float* __restrict__ D,
                                                float* __restrict__ out) {
    const int S = DMQ / 2;                       // row stride in pairs
    int c  = blockIdx.x * 256 + threadIdx.x;     // 0..511 channel pair
    int t0 = blockIdx.y * 16;
    int b  = blockIdx.z;

    const u64t* xp = reinterpret_cast<const u64t*>(x) + (size_t)b * LQ * S + c;
    u64t dp = reinterpret_cast<const u64t*>(D)[c];

    // Pre-sync: history x[t0-15 .. t0-1] into rolling slots 0..14
    u64t wbuf[16];
    #pragma unroll
    for (int i = 0; i < 15; i++) {
        int t = t0 - 15 + i;
        wbuf[i] = (t >= 0) ? xp[(size_t)t * S] : 0ull;   // 0x0 == {+0.f,+0.f}
    }

    cudaGridDependencySynchronize();             // wait for K2's g_k

    const u64t* kp = reinterpret_cast<const u64t*>(g_k) + (size_t)b * TAPS * S + c;
    u64t kr[TAPS];
    #pragma unroll
    for (int u = 0; u < TAPS; u++) kr[u] = kp[(size_t)u * S];

    u64t* op = reinterpret_cast<u64t*>(out) + (size_t)b * LQ * S + c;

    #pragma unroll
    for (int j = 0; j < 16; j++) {
        u64t xcur = xp[(size_t)(t0 + j) * S];
        wbuf[(15 + j) & 15] = xcur;              // overwrites t0+j-16 (dead)
        u64t a = fmul2(xcur, dp);                // D skip
        #pragma unroll
        for (int u = 0; u < TAPS; u++)
            a = ffma2(kr[u], wbuf[(15 + j - u) & 15], a);
        op[(size_t)(t0 + j) * S] = a;
    }
}

// ---------------------------------------------------------------------------
extern "C" void kernel_launch(void* const* d_in, const int* in_sizes, int n_in,
                              void* d_out, int out_size) {
    const float* x     = (const float*)d_in[0];   // (4, 2048, 1024)
    const float* W_B   = (const float*)d_in[1];   // (64, 1024)
    const float* b_B   = (const float*)d_in[2];   // (64,)
    const float* C     = (const float*)d_in[3];   // (64, 1024)
    const float* D     = (const float*)d_in[4];   // (1024,)
    const float* log_A = (const float*)d_in[5];   // (64,)
    float* out = (float*)d_out;

    s4_k1<<<1024, 128>>>(x, W_B, b_B, log_A);

    cudaLaunchAttribute attr[1];
    attr[0].id = cudaLaunchAttributeProgrammaticStreamSerialization;
    attr[0].val.programmaticStreamSerializationAllowed = 1;

    // K2 (PDL secondary to K1; plain fallback)
    {
        cudaLaunchConfig_t cfg = {};
        cfg.gridDim  = dim3(16, 16);
        cfg.blockDim = dim3(64, 4);
        cfg.stream = 0;
        cfg.attrs = attr;
        cfg.numAttrs = 1;
        cudaError_t e = cudaLaunchKernelEx(&cfg, s4_k2, C);
        if (e != cudaSuccess) {
            (void)cudaGetLastError();
            s4_k2<<<dim3(16, 16), dim3(64, 4)>>>(C);
        }
    }

    // K3 (PDL secondary to K2; plain fallback)
    {
        cudaLaunchConfig_t cfg = {};
        cfg.gridDim  = dim3(2, 128, 4);
        cfg.blockDim = dim3(256, 1, 1);
        cfg.stream = 0;
        cfg.attrs = attr;
        cfg.numAttrs = 1;
        cudaError_t e = cudaLaunchKernelEx(&cfg, s4_k3, x, D, (float*)out);
        if (e != cudaSuccess) {
            (void)cudaGetLastError();
            s4_k3<<<dim3(2, 128, 4), 256>>>(x, D, out);
        }
    }
}